// round 15
// baseline (speedup 1.0000x reference)
#include <cuda_runtime.h>
#include <cuda_bf16.h>
#include <cstdint>

#define NN 50000
#define NE 1600000
#define D  128
#define NBLK 196   // scan blocks (196*256 >= NN)

// ---------------- scratch (device globals; no allocation allowed) ----------
__device__ int   g_counts[NN];     // static zero-init; re-zeroed by k_mlp tail
__device__ int   g_offsets[NN];    // block-local exclusive offsets
__device__ int   g_blksum[NBLK];   // per-scan-block totals
__device__ int   g_pos[NE];
__device__ int   g_edge_ids[NE];
__device__ float g_agg[(size_t)NN * D];
__device__ float g_c0[D];
// frag-major pre-split weights: {hi0, hi1, lo0, lo1} per lane per (ntile,ktile)
__device__ uint4 g_W1f[8 * 16 * 2 * 32];   // K=256
__device__ uint4 g_W2f[16 * 8 * 32];       // K=128

// ---------------- helpers ----------------------------------------------------
__device__ __forceinline__ uint32_t pack_bf16(float x0, float x1) {
    __nv_bfloat162 h = __floats2bfloat162_rn(x0, x1);
    return *(uint32_t*)&h;
}
__device__ __forceinline__ void split_pair(float x0, float x1,
                                           uint32_t& hi, uint32_t& lo) {
    __nv_bfloat16 h0 = __float2bfloat16_rn(x0);
    __nv_bfloat16 h1 = __float2bfloat16_rn(x1);
    float l0 = x0 - __bfloat162float(h0);
    float l1 = x1 - __bfloat162float(h1);
    __nv_bfloat162 hp; hp.x = h0; hp.y = h1;
    hi = *(uint32_t*)&hp;
    lo = pack_bf16(l0, l1);
}
__device__ __forceinline__ void mma_bf16(float* d, uint32_t a0, uint32_t a1,
                                         uint32_t a2, uint32_t a3,
                                         uint32_t b0, uint32_t b1) {
    asm volatile(
        "mma.sync.aligned.m16n8k16.row.col.f32.bf16.bf16.f32 "
        "{%0,%1,%2,%3}, {%4,%5,%6,%7}, {%8,%9}, {%0,%1,%2,%3};"
        : "+f"(d[0]), "+f"(d[1]), "+f"(d[2]), "+f"(d[3])
        : "r"(a0), "r"(a1), "r"(a2), "r"(a3), "r"(b0), "r"(b1));
}
__device__ __forceinline__ float4 ldcs4(const float* p) {
    float4 v;
    asm volatile("ld.global.cs.v4.f32 {%0,%1,%2,%3}, [%4];"
                 : "=f"(v.x), "=f"(v.y), "=f"(v.z), "=f"(v.w) : "l"(p));
    return v;
}

// compute exclusive block-prefix table (196 entries) into se[] from g_blksum.
// call with full 256-thread block; leaves result in se; ends synced.
__device__ __forceinline__ void block_prefix(int* s, int* se) {
    int t = threadIdx.x;
    int v = (t < NBLK) ? g_blksum[t] : 0;
    s[t] = v;
    __syncthreads();
#pragma unroll
    for (int d = 1; d < 256; d <<= 1) {
        int add = (t >= d) ? s[t - d] : 0;
        __syncthreads();
        s[t] += add;
        __syncthreads();
    }
    se[t] = s[t] - v;   // exclusive prefix
    __syncthreads();
}

// ---------------- weight prep: c0 | bf16-split frags (side stream) ----------
__global__ void k_prep(const float* __restrict__ gattr,
                       const float* __restrict__ W1,
                       const float* __restrict__ b1,
                       const float* __restrict__ W2) {
    int b = blockIdx.x;
    if (b == 0) {
        if (threadIdx.x < 128) {
            int j = threadIdx.x;
            float s = b1[j];
            for (int k = 0; k < 128; k++)
                s += gattr[k] * W1[(size_t)(256 + k) * D + j];
            g_c0[j] = s;
        }
    } else {
        int i = (b - 1) * 256 + threadIdx.x;
        if (i < 8192) {
            int lane = i & 31, ntile = (i >> 5) & 15, ktile = i >> 9;
            int g = lane >> 2, c = lane & 3;
            int n = ntile * 8 + g;
            int k0 = ktile * 16 + 2 * c;
            float w0 = W1[(size_t)(k0 + 0) * D + n];
            float w1 = W1[(size_t)(k0 + 1) * D + n];
            float w8 = W1[(size_t)(k0 + 8) * D + n];
            float w9 = W1[(size_t)(k0 + 9) * D + n];
            uint4 o;
            split_pair(w0, w1, o.x, o.z);
            split_pair(w8, w9, o.y, o.w);
            int idx = (((ktile >> 1) * 16 + ntile) * 2 + (ktile & 1)) * 32 + lane;
            g_W1f[idx] = o;
        } else if (i < 8192 + 4096) {
            int j = i - 8192;
            int lane = j & 31, ntile = (j >> 5) & 15, ktile = j >> 9;
            int g = lane >> 2, c = lane & 3;
            int n = ntile * 8 + g;
            int k0 = ktile * 16 + 2 * c;
            float w0 = W2[(size_t)(k0 + 0) * D + n];
            float w1 = W2[(size_t)(k0 + 1) * D + n];
            float w8 = W2[(size_t)(k0 + 8) * D + n];
            float w9 = W2[(size_t)(k0 + 9) * D + n];
            uint4 o;
            split_pair(w0, w1, o.x, o.z);
            split_pair(w8, w9, o.y, o.w);
            g_W2f[(ntile * 8 + ktile) * 32 + lane] = o;
        }
    }
}

// ---------------- CSR build (single atomic pass, scalar R13 form) -----------
__global__ void k_count_pos(const int* __restrict__ dst) {
    int e = blockIdx.x * blockDim.x + threadIdx.x;
    if (e < NE) g_pos[e] = atomicAdd(&g_counts[dst[e]], 1);
}

// ---------------- block-local scan (phase 1 only) ----------------------------
__global__ void k_scan1() {
    __shared__ int s[256];
    int t = threadIdx.x;
    int i = blockIdx.x * 256 + t;
    int v = (i < NN) ? g_counts[i] : 0;
    s[t] = v;
    __syncthreads();
#pragma unroll
    for (int d = 1; d < 256; d <<= 1) {
        int add = (t >= d) ? s[t - d] : 0;
        __syncthreads();
        s[t] += add;
        __syncthreads();
    }
    if (i < NN) g_offsets[i] = s[t] - v;   // block-local exclusive
    if (t == 255) g_blksum[blockIdx.x] = s[255];
}

// ---------------- scatter (scalar R13 form + in-block prefix table) ---------
__global__ void k_scatter(const int* __restrict__ dst) {
    __shared__ int s[256];
    __shared__ int se[256];
    block_prefix(s, se);
    int e = blockIdx.x * blockDim.x + threadIdx.x;
    if (e < NE) {
        int d = dst[e];
        g_edge_ids[g_offsets[d] + se[d >> 8] + g_pos[e]] = e;
    }
}

// ---------------- warp-per-node segment mean (R4 body + prefix table) -------
__global__ void k_aggregate(const float* __restrict__ edge_attrs) {
    __shared__ int s[256];
    __shared__ int se[256];
    block_prefix(s, se);

    int warp = threadIdx.x >> 5;
    int lane = threadIdx.x & 31;
    int node = blockIdx.x * (blockDim.x >> 5) + warp;   // grid*8 == NN exactly

    int start = g_offsets[node] + se[node >> 8];
    int deg   = g_counts[node];

    float4 a0 = make_float4(0.f, 0.f, 0.f, 0.f);
    float4 a1 = make_float4(0.f, 0.f, 0.f, 0.f);
    float4 a2 = make_float4(0.f, 0.f, 0.f, 0.f);
    float4 a3 = make_float4(0.f, 0.f, 0.f, 0.f);
    int i = 0;
    for (; i + 3 < deg; i += 4) {
        int e0 = g_edge_ids[start + i];
        int e1 = g_edge_ids[start + i + 1];
        int e2 = g_edge_ids[start + i + 2];
        int e3 = g_edge_ids[start + i + 3];
        float4 v0 = ldcs4(edge_attrs + (size_t)e0 * D + lane * 4);
        float4 v1 = ldcs4(edge_attrs + (size_t)e1 * D + lane * 4);
        float4 v2 = ldcs4(edge_attrs + (size_t)e2 * D + lane * 4);
        float4 v3 = ldcs4(edge_attrs + (size_t)e3 * D + lane * 4);
        a0.x += v0.x; a0.y += v0.y; a0.z += v0.z; a0.w += v0.w;
        a1.x += v1.x; a1.y += v1.y; a1.z += v1.z; a1.w += v1.w;
        a2.x += v2.x; a2.y += v2.y; a2.z += v2.z; a2.w += v2.w;
        a3.x += v3.x; a3.y += v3.y; a3.z += v3.z; a3.w += v3.w;
    }
    for (; i < deg; i++) {
        int e0 = g_edge_ids[start + i];
        float4 v0 = ldcs4(edge_attrs + (size_t)e0 * D + lane * 4);
        a0.x += v0.x; a0.y += v0.y; a0.z += v0.z; a0.w += v0.w;
    }
    float inv = (deg > 0) ? (1.0f / (float)deg) : 0.0f;
    float4 r;
    r.x = (a0.x + a1.x + a2.x + a3.x) * inv;
    r.y = (a0.y + a1.y + a2.y + a3.y) * inv;
    r.z = (a0.z + a1.z + a2.z + a3.z) * inv;
    r.w = (a0.w + a1.w + a2.w + a3.w) * inv;
    *((float4*)(g_agg + (size_t)node * D) + lane) = r;
}

// ---------------- fused 2-layer MLP: A via smem, B direct from global -------
// smem: A stages 2x16KB @0, A2 frags 64KB @32KB -> 96KB total, 2 CTAs/SM
#define SM_SA(s) ((s) * 16384)
#define SM_A2 32768
#define MLP_SMEM 98304

__device__ __forceinline__ void mma_block_g(const char* sm, uint32_t abase,
                                            const uint4* __restrict__ wbase,
                                            int KT, int kt, int ktN,
                                            int wm, int wn, int lane,
                                            float Dm[2][8][4]) {
    uint4 ah[2], al[2];
#pragma unroll
    for (int mt = 0; mt < 2; mt++) {
        const uint4* p = (const uint4*)(sm + abase +
            (uint32_t)((((wm * 2 + mt) * KT + kt) * 32 + lane) * 32));
        ah[mt] = p[0];
        al[mt] = p[1];
    }
#pragma unroll
    for (int nt = 0; nt < 8; nt++) {
        uint4 b = __ldg(&wbase[(((wn * 8 + nt) * ktN) + kt) * 32 + lane]);
#pragma unroll
        for (int mt = 0; mt < 2; mt++) {
            mma_bf16(Dm[mt][nt], ah[mt].x, ah[mt].y, ah[mt].z, ah[mt].w, b.x, b.y);
            mma_bf16(Dm[mt][nt], ah[mt].x, ah[mt].y, ah[mt].z, ah[mt].w, b.z, b.w);
            mma_bf16(Dm[mt][nt], al[mt].x, al[mt].y, al[mt].z, al[mt].w, b.x, b.y);
        }
    }
}

__global__ void __launch_bounds__(256, 2)
k_mlp(const float* __restrict__ agg, const float* __restrict__ node,
      const float* __restrict__ c0, const float* __restrict__ b2,
      float* __restrict__ out) {
    extern __shared__ char sm[];
    int tid = threadIdx.x, lane = tid & 31, wid = tid >> 5;
    int wm = wid >> 1, wn = wid & 1;
    int m0 = blockIdx.x * 128;

    int srow = tid >> 1;
    int skt  = tid & 1;
    int smt  = srow >> 4;
    int slan = (srow & 7) * 4;
    int srh  = (srow >> 3) & 1;
    int gm   = m0 + srow;
    bool mok = (gm < NN);

    float D1[2][8][4];
#pragma unroll
    for (int a = 0; a < 2; a++)
#pragma unroll
        for (int b = 0; b < 8; b++)
#pragma unroll
            for (int q = 0; q < 4; q++) D1[a][b][q] = 0.f;

    float4 va[4];
    {
        int kc = skt * 16;
#pragma unroll
        for (int q = 0; q < 4; q++)
            va[q] = mok ? *(const float4*)(agg + (size_t)gm * D + kc + q * 4)
                        : make_float4(0.f, 0.f, 0.f, 0.f);
    }

    for (int s = 0; s < 8; s++) {
        int buf = s & 1;
        {
            float xs[16];
#pragma unroll
            for (int q = 0; q < 4; q++) {
                xs[q * 4 + 0] = va[q].x; xs[q * 4 + 1] = va[q].y;
                xs[q * 4 + 2] = va[q].z; xs[q * 4 + 3] = va[q].w;
            }
            uint32_t abase = SM_SA(buf) + (uint32_t)(((smt * 2 + skt) * 32) * 32);
#pragma unroll
            for (int p = 0; p < 8; p++) {
                uint32_t hi, lo;
                split_pair(xs[2 * p], xs[2 * p + 1], hi, lo);
                int c = p & 3, j = p >> 2;
                uint32_t off = abase + (uint32_t)((slan + c) * 32 + (srh + 2 * j) * 4);
                *(uint32_t*)(sm + off)      = hi;
                *(uint32_t*)(sm + off + 16) = lo;
            }
        }
        __syncthreads();
        if (s < 7) {
            const float* src = (s + 1 < 4) ? agg : node;
            int kc = ((s + 1) & 3) * 32 + skt * 16;
#pragma unroll
            for (int q = 0; q < 4; q++)
                va[q] = mok ? *(const float4*)(src + (size_t)gm * D + kc + q * 4)
                            : make_float4(0.f, 0.f, 0.f, 0.f);
        }
        const uint4* wb = g_W1f + s * 1024;
        mma_block_g(sm, SM_SA(buf), wb, 2, 0, 2, wm, wn, lane, D1);
        mma_block_g(sm, SM_SA(buf), wb, 2, 1, 2, wm, wn, lane, D1);
    }

    // epilogue-1: h = relu(D1 + c0) -> frag-major A2 (bf16 hi/lo)
    {
        int c = lane & 3;
#pragma unroll
        for (int mt = 0; mt < 2; mt++) {
#pragma unroll
            for (int nt = 0; nt < 8; nt++) {
                int col = wn * 64 + nt * 8 + 2 * c;
                float2 cv = *(const float2*)(c0 + col);
                float h0 = fmaxf(D1[mt][nt][0] + cv.x, 0.f);
                float h1 = fmaxf(D1[mt][nt][1] + cv.y, 0.f);
                float h2 = fmaxf(D1[mt][nt][2] + cv.x, 0.f);
                float h3 = fmaxf(D1[mt][nt][3] + cv.y, 0.f);
                uint32_t hi0, lo0, hi1, lo1;
                split_pair(h0, h1, hi0, lo0);
                split_pair(h2, h3, hi1, lo1);
                int mtile2 = wm * 2 + mt;
                int ktile2 = wn * 4 + (nt >> 1);
                int j2 = nt & 1;
                uint32_t base = SM_A2 +
                    (uint32_t)(((mtile2 * 8 + ktile2) * 32 + lane) * 32);
                *(uint32_t*)(sm + base + (0 + 2 * j2) * 4)      = hi0;
                *(uint32_t*)(sm + base + (0 + 2 * j2) * 4 + 16) = lo0;
                *(uint32_t*)(sm + base + (1 + 2 * j2) * 4)      = hi1;
                *(uint32_t*)(sm + base + (1 + 2 * j2) * 4 + 16) = lo1;
            }
        }
    }
    __syncthreads();

    float D2[2][8][4];
#pragma unroll
    for (int a = 0; a < 2; a++)
#pragma unroll
        for (int b = 0; b < 8; b++)
#pragma unroll
            for (int q = 0; q < 4; q++) D2[a][b][q] = 0.f;
#pragma unroll
    for (int kt = 0; kt < 8; kt++)
        mma_block_g(sm, SM_A2, g_W2f, 8, kt, 8, wm, wn, lane, D2);

    {
        int c = lane & 3, g = lane >> 2;
#pragma unroll
        for (int mt = 0; mt < 2; mt++) {
            int mrow = m0 + wm * 32 + mt * 16 + g;
#pragma unroll
            for (int nt = 0; nt < 8; nt++) {
                int col = wn * 64 + nt * 8 + 2 * c;
                float2 bv = *(const float2*)(b2 + col);
                if (mrow < NN) {
                    float2 o0 = make_float2(D2[mt][nt][0] + bv.x,
                                            D2[mt][nt][1] + bv.y);
                    *(float2*)(out + (size_t)mrow * D + col) = o0;
                }
                if (mrow + 8 < NN) {
                    float2 o1 = make_float2(D2[mt][nt][2] + bv.x,
                                            D2[mt][nt][3] + bv.y);
                    *(float2*)(out + (size_t)(mrow + 8) * D + col) = o1;
                }
            }
        }
    }

    // tail: re-zero counts for the next graph replay (counts are dead here;
    // first call relies on static zero-init). 391 blocks x 256 threads > NN.
    int gt = blockIdx.x * 256 + tid;
    if (gt < NN) g_counts[gt] = 0;
}

// ---------------- launch -----------------------------------------------------
extern "C" void kernel_launch(void* const* d_in, const int* in_sizes, int n_in,
                              void* d_out, int out_size) {
    const float* edge_attrs = (const float*)d_in[0];
    const float* node_attrs = (const float*)d_in[1];
    const float* gattr      = (const float*)d_in[2];
    const float* W1         = (const float*)d_in[3];
    const float* b1         = (const float*)d_in[4];
    const float* W2         = (const float*)d_in[5];
    const float* b2         = (const float*)d_in[6];
    const int*   edge_dst   = (const int*)d_in[7];
    float*       out        = (float*)d_out;

    float* agg_p; cudaGetSymbolAddress((void**)&agg_p, g_agg);
    float* c0_p;  cudaGetSymbolAddress((void**)&c0_p,  g_c0);

    static cudaStream_t s_side = nullptr;
    static cudaEvent_t  ev_prep = nullptr, ev_fork = nullptr;
    if (!s_side) {   // first call is the (non-captured) correctness run
        cudaStreamCreateWithFlags(&s_side, cudaStreamNonBlocking);
        cudaEventCreateWithFlags(&ev_prep, cudaEventDisableTiming);
        cudaEventCreateWithFlags(&ev_fork, cudaEventDisableTiming);
        cudaFuncSetAttribute(k_mlp, cudaFuncAttributeMaxDynamicSharedMemorySize,
                             MLP_SMEM);
    }

    // fork point: weight prep overlaps the CSR chain on a side stream
    cudaEventRecord(ev_fork, 0);
    cudaStreamWaitEvent(s_side, ev_fork, 0);
    k_prep<<<49, 256, 0, s_side>>>(gattr, W1, b1, W2);
    cudaEventRecord(ev_prep, s_side);

    k_count_pos<<<(NE + 255) / 256, 256>>>(edge_dst);
    k_scan1<<<NBLK, 256>>>();
    k_scatter<<<(NE + 255) / 256, 256>>>(edge_dst);
    k_aggregate<<<(NN + 7) / 8, 256>>>(edge_attrs);

    cudaStreamWaitEvent(0, ev_prep, 0);
    int mb = (NN + 127) / 128;
    k_mlp<<<mb, 256, MLP_SMEM>>>(agg_p, node_attrs, c0_p, b2, out);
}

// round 16
// speedup vs baseline: 1.0886x; 1.0886x over previous
#include <cuda_runtime.h>
#include <cuda_bf16.h>
#include <cstdint>

#define NN 50000
#define NE 1600000
#define D  128
#define NBLK 196   // scan blocks (196*256 >= NN)

// ---------------- scratch (device globals; no allocation allowed) ----------
__device__ int   g_counts[NN];     // static zero-init; re-zeroed by k_mlp tail
__device__ int   g_offsets[NN];    // block-local exclusive offsets
__device__ int   g_blksum[NBLK];
__device__ int   g_blkpre[NBLK];   // exclusive block prefixes
__device__ int   g_pos[NE];
__device__ int   g_edge_ids[NE];
__device__ float g_agg[(size_t)NN * D];
__device__ float g_c0[D];
// frag-major pre-split weights: {hi0, hi1, lo0, lo1} per lane per (ntile,ktile)
__device__ uint4 g_W1f[8 * 16 * 2 * 32];   // K=256
__device__ uint4 g_W2f[16 * 8 * 32];       // K=128

// ---------------- helpers ----------------------------------------------------
__device__ __forceinline__ uint32_t pack_bf16(float x0, float x1) {
    __nv_bfloat162 h = __floats2bfloat162_rn(x0, x1);
    return *(uint32_t*)&h;
}
__device__ __forceinline__ void split_pair(float x0, float x1,
                                           uint32_t& hi, uint32_t& lo) {
    __nv_bfloat16 h0 = __float2bfloat16_rn(x0);
    __nv_bfloat16 h1 = __float2bfloat16_rn(x1);
    float l0 = x0 - __bfloat162float(h0);
    float l1 = x1 - __bfloat162float(h1);
    __nv_bfloat162 hp; hp.x = h0; hp.y = h1;
    hi = *(uint32_t*)&hp;
    lo = pack_bf16(l0, l1);
}
__device__ __forceinline__ void mma_bf16(float* d, uint32_t a0, uint32_t a1,
                                         uint32_t a2, uint32_t a3,
                                         uint32_t b0, uint32_t b1) {
    asm volatile(
        "mma.sync.aligned.m16n8k16.row.col.f32.bf16.bf16.f32 "
        "{%0,%1,%2,%3}, {%4,%5,%6,%7}, {%8,%9}, {%0,%1,%2,%3};"
        : "+f"(d[0]), "+f"(d[1]), "+f"(d[2]), "+f"(d[3])
        : "r"(a0), "r"(a1), "r"(a2), "r"(a3), "r"(b0), "r"(b1));
}
__device__ __forceinline__ float4 ldcs4(const float* p) {
    float4 v;
    asm volatile("ld.global.cs.v4.f32 {%0,%1,%2,%3}, [%4];"
                 : "=f"(v.x), "=f"(v.y), "=f"(v.z), "=f"(v.w) : "l"(p));
    return v;
}

// ---------------- weight prep: c0 | bf16-split frags (side stream) ----------
__global__ void k_prep(const float* __restrict__ gattr,
                       const float* __restrict__ W1,
                       const float* __restrict__ b1,
                       const float* __restrict__ W2) {
    int b = blockIdx.x;
    if (b == 0) {
        if (threadIdx.x < 128) {
            int j = threadIdx.x;
            float s = b1[j];
            for (int k = 0; k < 128; k++)
                s += gattr[k] * W1[(size_t)(256 + k) * D + j];
            g_c0[j] = s;
        }
    } else {
        int i = (b - 1) * 256 + threadIdx.x;
        if (i < 8192) {
            int lane = i & 31, ntile = (i >> 5) & 15, ktile = i >> 9;
            int g = lane >> 2, c = lane & 3;
            int n = ntile * 8 + g;
            int k0 = ktile * 16 + 2 * c;
            float w0 = W1[(size_t)(k0 + 0) * D + n];
            float w1 = W1[(size_t)(k0 + 1) * D + n];
            float w8 = W1[(size_t)(k0 + 8) * D + n];
            float w9 = W1[(size_t)(k0 + 9) * D + n];
            uint4 o;
            split_pair(w0, w1, o.x, o.z);
            split_pair(w8, w9, o.y, o.w);
            int idx = (((ktile >> 1) * 16 + ntile) * 2 + (ktile & 1)) * 32 + lane;
            g_W1f[idx] = o;
        } else if (i < 8192 + 4096) {
            int j = i - 8192;
            int lane = j & 31, ntile = (j >> 5) & 15, ktile = j >> 9;
            int g = lane >> 2, c = lane & 3;
            int n = ntile * 8 + g;
            int k0 = ktile * 16 + 2 * c;
            float w0 = W2[(size_t)(k0 + 0) * D + n];
            float w1 = W2[(size_t)(k0 + 1) * D + n];
            float w8 = W2[(size_t)(k0 + 8) * D + n];
            float w9 = W2[(size_t)(k0 + 9) * D + n];
            uint4 o;
            split_pair(w0, w1, o.x, o.z);
            split_pair(w8, w9, o.y, o.w);
            g_W2f[(ntile * 8 + ktile) * 32 + lane] = o;
        }
    }
}

// ---------------- CSR build (single atomic pass) ----------------------------
__global__ void k_count_pos(const int* __restrict__ dst) {
    int e = blockIdx.x * blockDim.x + threadIdx.x;
    if (e < NE) g_pos[e] = atomicAdd(&g_counts[dst[e]], 1);
}

// ---------------- 2-phase parallel scan (block-local + block prefixes) ------
__global__ void k_scan1() {
    __shared__ int s[256];
    int t = threadIdx.x;
    int i = blockIdx.x * 256 + t;
    int v = (i < NN) ? g_counts[i] : 0;
    s[t] = v;
    __syncthreads();
#pragma unroll
    for (int d = 1; d < 256; d <<= 1) {
        int add = (t >= d) ? s[t - d] : 0;
        __syncthreads();
        s[t] += add;
        __syncthreads();
    }
    if (i < NN) g_offsets[i] = s[t] - v;   // block-local exclusive
    if (t == 255) g_blksum[blockIdx.x] = s[255];
}

__global__ void k_scan2() {
    __shared__ int s[256];
    int t = threadIdx.x;
    int v = (t < NBLK) ? g_blksum[t] : 0;
    s[t] = v;
    __syncthreads();
#pragma unroll
    for (int d = 1; d < 256; d <<= 1) {
        int add = (t >= d) ? s[t - d] : 0;
        __syncthreads();
        s[t] += add;
        __syncthreads();
    }
    if (t < NBLK) g_blkpre[t] = s[t] - v;  // exclusive block prefix
}

__global__ void k_scatter(const int* __restrict__ dst) {
    int e = blockIdx.x * blockDim.x + threadIdx.x;
    if (e < NE) {
        int d = dst[e];
        g_edge_ids[g_offsets[d] + g_blkpre[d >> 8] + g_pos[e]] = e;
    }
}

// ---------------- warp-per-node segment mean (R4 body, occ-capped) ----------
__global__ void __launch_bounds__(256, 6)
k_aggregate(const float* __restrict__ edge_attrs) {
    int warp = threadIdx.x >> 5;
    int lane = threadIdx.x & 31;
    int node = blockIdx.x * (blockDim.x >> 5) + warp;
    if (node >= NN) return;

    int start = g_offsets[node] + g_blkpre[node >> 8];
    int deg   = g_counts[node];

    float4 a0 = make_float4(0.f, 0.f, 0.f, 0.f);
    float4 a1 = make_float4(0.f, 0.f, 0.f, 0.f);
    float4 a2 = make_float4(0.f, 0.f, 0.f, 0.f);
    float4 a3 = make_float4(0.f, 0.f, 0.f, 0.f);
    int i = 0;
    for (; i + 3 < deg; i += 4) {
        int e0 = g_edge_ids[start + i];
        int e1 = g_edge_ids[start + i + 1];
        int e2 = g_edge_ids[start + i + 2];
        int e3 = g_edge_ids[start + i + 3];
        float4 v0 = ldcs4(edge_attrs + (size_t)e0 * D + lane * 4);
        float4 v1 = ldcs4(edge_attrs + (size_t)e1 * D + lane * 4);
        float4 v2 = ldcs4(edge_attrs + (size_t)e2 * D + lane * 4);
        float4 v3 = ldcs4(edge_attrs + (size_t)e3 * D + lane * 4);
        a0.x += v0.x; a0.y += v0.y; a0.z += v0.z; a0.w += v0.w;
        a1.x += v1.x; a1.y += v1.y; a1.z += v1.z; a1.w += v1.w;
        a2.x += v2.x; a2.y += v2.y; a2.z += v2.z; a2.w += v2.w;
        a3.x += v3.x; a3.y += v3.y; a3.z += v3.z; a3.w += v3.w;
    }
    for (; i < deg; i++) {
        int e0 = g_edge_ids[start + i];
        float4 v0 = ldcs4(edge_attrs + (size_t)e0 * D + lane * 4);
        a0.x += v0.x; a0.y += v0.y; a0.z += v0.z; a0.w += v0.w;
    }
    float inv = (deg > 0) ? (1.0f / (float)deg) : 0.0f;
    float4 r;
    r.x = (a0.x + a1.x + a2.x + a3.x) * inv;
    r.y = (a0.y + a1.y + a2.y + a3.y) * inv;
    r.z = (a0.z + a1.z + a2.z + a3.z) * inv;
    r.w = (a0.w + a1.w + a2.w + a3.w) * inv;
    *((float4*)(g_agg + (size_t)node * D) + lane) = r;
}

// ---------------- fused 2-layer MLP: A via smem, B direct from global -------
// smem: A stages 2x16KB @0, A2 frags 64KB @32KB -> 96KB total, 2 CTAs/SM
#define SM_SA(s) ((s) * 16384)
#define SM_A2 32768
#define MLP_SMEM 98304

__device__ __forceinline__ void mma_block_g(const char* sm, uint32_t abase,
                                            const uint4* __restrict__ wbase,
                                            int KT, int kt, int ktN,
                                            int wm, int wn, int lane,
                                            float Dm[2][8][4]) {
    uint4 ah[2], al[2];
#pragma unroll
    for (int mt = 0; mt < 2; mt++) {
        const uint4* p = (const uint4*)(sm + abase +
            (uint32_t)((((wm * 2 + mt) * KT + kt) * 32 + lane) * 32));
        ah[mt] = p[0];
        al[mt] = p[1];
    }
#pragma unroll
    for (int nt = 0; nt < 8; nt++) {
        uint4 b = __ldg(&wbase[(((wn * 8 + nt) * ktN) + kt) * 32 + lane]);
#pragma unroll
        for (int mt = 0; mt < 2; mt++) {
            mma_bf16(Dm[mt][nt], ah[mt].x, ah[mt].y, ah[mt].z, ah[mt].w, b.x, b.y);
            mma_bf16(Dm[mt][nt], ah[mt].x, ah[mt].y, ah[mt].z, ah[mt].w, b.z, b.w);
            mma_bf16(Dm[mt][nt], al[mt].x, al[mt].y, al[mt].z, al[mt].w, b.x, b.y);
        }
    }
}

__global__ void __launch_bounds__(256, 2)
k_mlp(const float* __restrict__ agg, const float* __restrict__ node,
      const float* __restrict__ c0, const float* __restrict__ b2,
      float* __restrict__ out) {
    extern __shared__ char sm[];
    int tid = threadIdx.x, lane = tid & 31, wid = tid >> 5;
    int wm = wid >> 1, wn = wid & 1;
    int m0 = blockIdx.x * 128;

    int srow = tid >> 1;
    int skt  = tid & 1;
    int smt  = srow >> 4;
    int slan = (srow & 7) * 4;
    int srh  = (srow >> 3) & 1;
    int gm   = m0 + srow;
    bool mok = (gm < NN);

    float D1[2][8][4];
#pragma unroll
    for (int a = 0; a < 2; a++)
#pragma unroll
        for (int b = 0; b < 8; b++)
#pragma unroll
            for (int q = 0; q < 4; q++) D1[a][b][q] = 0.f;

    float4 va[4];
    {
        int kc = skt * 16;
#pragma unroll
        for (int q = 0; q < 4; q++)
            va[q] = mok ? *(const float4*)(agg + (size_t)gm * D + kc + q * 4)
                        : make_float4(0.f, 0.f, 0.f, 0.f);
    }

    for (int s = 0; s < 8; s++) {
        int buf = s & 1;
        {
            float xs[16];
#pragma unroll
            for (int q = 0; q < 4; q++) {
                xs[q * 4 + 0] = va[q].x; xs[q * 4 + 1] = va[q].y;
                xs[q * 4 + 2] = va[q].z; xs[q * 4 + 3] = va[q].w;
            }
            uint32_t abase = SM_SA(buf) + (uint32_t)(((smt * 2 + skt) * 32) * 32);
#pragma unroll
            for (int p = 0; p < 8; p++) {
                uint32_t hi, lo;
                split_pair(xs[2 * p], xs[2 * p + 1], hi, lo);
                int c = p & 3, j = p >> 2;
                uint32_t off = abase + (uint32_t)((slan + c) * 32 + (srh + 2 * j) * 4);
                *(uint32_t*)(sm + off)      = hi;
                *(uint32_t*)(sm + off + 16) = lo;
            }
        }
        __syncthreads();
        if (s < 7) {
            const float* src = (s + 1 < 4) ? agg : node;
            int kc = ((s + 1) & 3) * 32 + skt * 16;
#pragma unroll
            for (int q = 0; q < 4; q++)
                va[q] = mok ? *(const float4*)(src + (size_t)gm * D + kc + q * 4)
                            : make_float4(0.f, 0.f, 0.f, 0.f);
        }
        const uint4* wb = g_W1f + s * 1024;
        mma_block_g(sm, SM_SA(buf), wb, 2, 0, 2, wm, wn, lane, D1);
        mma_block_g(sm, SM_SA(buf), wb, 2, 1, 2, wm, wn, lane, D1);
    }

    // epilogue-1: h = relu(D1 + c0) -> frag-major A2 (bf16 hi/lo)
    {
        int c = lane & 3;
#pragma unroll
        for (int mt = 0; mt < 2; mt++) {
#pragma unroll
            for (int nt = 0; nt < 8; nt++) {
                int col = wn * 64 + nt * 8 + 2 * c;
                float2 cv = *(const float2*)(c0 + col);
                float h0 = fmaxf(D1[mt][nt][0] + cv.x, 0.f);
                float h1 = fmaxf(D1[mt][nt][1] + cv.y, 0.f);
                float h2 = fmaxf(D1[mt][nt][2] + cv.x, 0.f);
                float h3 = fmaxf(D1[mt][nt][3] + cv.y, 0.f);
                uint32_t hi0, lo0, hi1, lo1;
                split_pair(h0, h1, hi0, lo0);
                split_pair(h2, h3, hi1, lo1);
                int mtile2 = wm * 2 + mt;
                int ktile2 = wn * 4 + (nt >> 1);
                int j2 = nt & 1;
                uint32_t base = SM_A2 +
                    (uint32_t)(((mtile2 * 8 + ktile2) * 32 + lane) * 32);
                *(uint32_t*)(sm + base + (0 + 2 * j2) * 4)      = hi0;
                *(uint32_t*)(sm + base + (0 + 2 * j2) * 4 + 16) = lo0;
                *(uint32_t*)(sm + base + (1 + 2 * j2) * 4)      = hi1;
                *(uint32_t*)(sm + base + (1 + 2 * j2) * 4 + 16) = lo1;
            }
        }
    }
    __syncthreads();

    float D2[2][8][4];
#pragma unroll
    for (int a = 0; a < 2; a++)
#pragma unroll
        for (int b = 0; b < 8; b++)
#pragma unroll
            for (int q = 0; q < 4; q++) D2[a][b][q] = 0.f;
#pragma unroll
    for (int kt = 0; kt < 8; kt++)
        mma_block_g(sm, SM_A2, g_W2f, 8, kt, 8, wm, wn, lane, D2);

    {
        int c = lane & 3, g = lane >> 2;
#pragma unroll
        for (int mt = 0; mt < 2; mt++) {
            int mrow = m0 + wm * 32 + mt * 16 + g;
#pragma unroll
            for (int nt = 0; nt < 8; nt++) {
                int col = wn * 64 + nt * 8 + 2 * c;
                float2 bv = *(const float2*)(b2 + col);
                if (mrow < NN) {
                    float2 o0 = make_float2(D2[mt][nt][0] + bv.x,
                                            D2[mt][nt][1] + bv.y);
                    *(float2*)(out + (size_t)mrow * D + col) = o0;
                }
                if (mrow + 8 < NN) {
                    float2 o1 = make_float2(D2[mt][nt][2] + bv.x,
                                            D2[mt][nt][3] + bv.y);
                    *(float2*)(out + (size_t)(mrow + 8) * D + col) = o1;
                }
            }
        }
    }

    // tail: re-zero counts for the next graph replay (counts are dead here;
    // first call relies on static zero-init). 391 blocks x 256 threads > NN.
    int gt = blockIdx.x * 256 + tid;
    if (gt < NN) g_counts[gt] = 0;
}

// ---------------- launch -----------------------------------------------------
extern "C" void kernel_launch(void* const* d_in, const int* in_sizes, int n_in,
                              void* d_out, int out_size) {
    const float* edge_attrs = (const float*)d_in[0];
    const float* node_attrs = (const float*)d_in[1];
    const float* gattr      = (const float*)d_in[2];
    const float* W1         = (const float*)d_in[3];
    const float* b1         = (const float*)d_in[4];
    const float* W2         = (const float*)d_in[5];
    const float* b2         = (const float*)d_in[6];
    const int*   edge_dst   = (const int*)d_in[7];
    float*       out        = (float*)d_out;

    float* agg_p; cudaGetSymbolAddress((void**)&agg_p, g_agg);
    float* c0_p;  cudaGetSymbolAddress((void**)&c0_p,  g_c0);

    static cudaStream_t s_side = nullptr;
    static cudaEvent_t  ev_prep = nullptr, ev_fork = nullptr;
    if (!s_side) {   // first call is the (non-captured) correctness run
        cudaStreamCreateWithFlags(&s_side, cudaStreamNonBlocking);
        cudaEventCreateWithFlags(&ev_prep, cudaEventDisableTiming);
        cudaEventCreateWithFlags(&ev_fork, cudaEventDisableTiming);
        cudaFuncSetAttribute(k_mlp, cudaFuncAttributeMaxDynamicSharedMemorySize,
                             MLP_SMEM);
    }

    // fork point: weight prep overlaps the CSR chain on a side stream
    cudaEventRecord(ev_fork, 0);
    cudaStreamWaitEvent(s_side, ev_fork, 0);
    k_prep<<<49, 256, 0, s_side>>>(gattr, W1, b1, W2);
    cudaEventRecord(ev_prep, s_side);

    k_count_pos<<<(NE + 255) / 256, 256>>>(edge_dst);
    k_scan1<<<NBLK, 256>>>();
    k_scan2<<<1, 256>>>();
    k_scatter<<<(NE + 255) / 256, 256>>>(edge_dst);
    k_aggregate<<<(NN + 7) / 8, 256>>>(edge_attrs);

    cudaStreamWaitEvent(0, ev_prep, 0);
    int mb = (NN + 127) / 128;
    k_mlp<<<mb, 256, MLP_SMEM>>>(agg_p, node_attrs, c0_p, b2, out);
}

// round 17
// speedup vs baseline: 1.0974x; 1.0082x over previous
#include <cuda_runtime.h>
#include <cuda_bf16.h>
#include <cstdint>

#define NN 50000
#define NE 1600000
#define D  128
#define NBLK 196   // scan blocks (196*256 >= NN)

// ---------------- scratch (device globals; no allocation allowed) ----------
__device__ int   g_counts[NN];     // static zero-init; re-zeroed by k_mlp tail
__device__ int   g_offsets[NN];    // block-local exclusive offsets
__device__ int   g_blksum[NBLK];
__device__ int   g_blkpre[NBLK];   // exclusive block prefixes
__device__ int   g_pos[NE];
__device__ int   g_edge_ids[NE];
__device__ float g_agg[(size_t)NN * D];
__device__ float g_c0[D];
// frag-major pre-split weights: {hi0, hi1, lo0, lo1} per lane per (ntile,ktile)
__device__ uint4 g_W1f[8 * 16 * 2 * 32];   // K=256
__device__ uint4 g_W2f[16 * 8 * 32];       // K=128

// ---------------- helpers ----------------------------------------------------
__device__ __forceinline__ uint32_t pack_bf16(float x0, float x1) {
    __nv_bfloat162 h = __floats2bfloat162_rn(x0, x1);
    return *(uint32_t*)&h;
}
__device__ __forceinline__ void split_pair(float x0, float x1,
                                           uint32_t& hi, uint32_t& lo) {
    __nv_bfloat16 h0 = __float2bfloat16_rn(x0);
    __nv_bfloat16 h1 = __float2bfloat16_rn(x1);
    float l0 = x0 - __bfloat162float(h0);
    float l1 = x1 - __bfloat162float(h1);
    __nv_bfloat162 hp; hp.x = h0; hp.y = h1;
    hi = *(uint32_t*)&hp;
    lo = pack_bf16(l0, l1);
}
__device__ __forceinline__ void mma_bf16(float* d, uint32_t a0, uint32_t a1,
                                         uint32_t a2, uint32_t a3,
                                         uint32_t b0, uint32_t b1) {
    asm volatile(
        "mma.sync.aligned.m16n8k16.row.col.f32.bf16.bf16.f32 "
        "{%0,%1,%2,%3}, {%4,%5,%6,%7}, {%8,%9}, {%0,%1,%2,%3};"
        : "+f"(d[0]), "+f"(d[1]), "+f"(d[2]), "+f"(d[3])
        : "r"(a0), "r"(a1), "r"(a2), "r"(a3), "r"(b0), "r"(b1));
}
__device__ __forceinline__ float4 ldcs4(const float* p) {
    float4 v;
    asm volatile("ld.global.cs.v4.f32 {%0,%1,%2,%3}, [%4];"
                 : "=f"(v.x), "=f"(v.y), "=f"(v.z), "=f"(v.w) : "l"(p));
    return v;
}

// ---------------- weight prep: c0 | bf16-split frags (side stream) ----------
__global__ void k_prep(const float* __restrict__ gattr,
                       const float* __restrict__ W1,
                       const float* __restrict__ b1,
                       const float* __restrict__ W2) {
    int b = blockIdx.x;
    if (b == 0) {
        if (threadIdx.x < 128) {
            int j = threadIdx.x;
            float s = b1[j];
            for (int k = 0; k < 128; k++)
                s += gattr[k] * W1[(size_t)(256 + k) * D + j];
            g_c0[j] = s;
        }
    } else {
        int i = (b - 1) * 256 + threadIdx.x;
        if (i < 8192) {
            int lane = i & 31, ntile = (i >> 5) & 15, ktile = i >> 9;
            int g = lane >> 2, c = lane & 3;
            int n = ntile * 8 + g;
            int k0 = ktile * 16 + 2 * c;
            float w0 = W1[(size_t)(k0 + 0) * D + n];
            float w1 = W1[(size_t)(k0 + 1) * D + n];
            float w8 = W1[(size_t)(k0 + 8) * D + n];
            float w9 = W1[(size_t)(k0 + 9) * D + n];
            uint4 o;
            split_pair(w0, w1, o.x, o.z);
            split_pair(w8, w9, o.y, o.w);
            int idx = (((ktile >> 1) * 16 + ntile) * 2 + (ktile & 1)) * 32 + lane;
            g_W1f[idx] = o;
        } else if (i < 8192 + 4096) {
            int j = i - 8192;
            int lane = j & 31, ntile = (j >> 5) & 15, ktile = j >> 9;
            int g = lane >> 2, c = lane & 3;
            int n = ntile * 8 + g;
            int k0 = ktile * 16 + 2 * c;
            float w0 = W2[(size_t)(k0 + 0) * D + n];
            float w1 = W2[(size_t)(k0 + 1) * D + n];
            float w8 = W2[(size_t)(k0 + 8) * D + n];
            float w9 = W2[(size_t)(k0 + 9) * D + n];
            uint4 o;
            split_pair(w0, w1, o.x, o.z);
            split_pair(w8, w9, o.y, o.w);
            g_W2f[(ntile * 8 + ktile) * 32 + lane] = o;
        }
    }
}

// ---------------- CSR build (single atomic pass) ----------------------------
__global__ void k_count_pos(const int* __restrict__ dst) {
    int e = blockIdx.x * blockDim.x + threadIdx.x;
    if (e < NE) g_pos[e] = atomicAdd(&g_counts[dst[e]], 1);
}

// ---------------- 2-phase parallel scan (block-local + block prefixes) ------
__global__ void k_scan1() {
    __shared__ int s[256];
    int t = threadIdx.x;
    int i = blockIdx.x * 256 + t;
    int v = (i < NN) ? g_counts[i] : 0;
    s[t] = v;
    __syncthreads();
#pragma unroll
    for (int d = 1; d < 256; d <<= 1) {
        int add = (t >= d) ? s[t - d] : 0;
        __syncthreads();
        s[t] += add;
        __syncthreads();
    }
    if (i < NN) g_offsets[i] = s[t] - v;   // block-local exclusive
    if (t == 255) g_blksum[blockIdx.x] = s[255];
}

__global__ void k_scan2() {
    __shared__ int s[256];
    int t = threadIdx.x;
    int v = (t < NBLK) ? g_blksum[t] : 0;
    s[t] = v;
    __syncthreads();
#pragma unroll
    for (int d = 1; d < 256; d <<= 1) {
        int add = (t >= d) ? s[t - d] : 0;
        __syncthreads();
        s[t] += add;
        __syncthreads();
    }
    if (t < NBLK) g_blkpre[t] = s[t] - v;  // exclusive block prefix
}

__global__ void k_scatter(const int* __restrict__ dst) {
    int e = blockIdx.x * blockDim.x + threadIdx.x;
    if (e < NE) {
        int d = dst[e];
        g_edge_ids[g_offsets[d] + g_blkpre[d >> 8] + g_pos[e]] = e;
    }
}

// ---------------- warp-per-node segment mean (occ 8 CTAs/SM, 2 acc) ---------
__global__ void __launch_bounds__(256, 8)
k_aggregate(const float* __restrict__ edge_attrs) {
    int warp = threadIdx.x >> 5;
    int lane = threadIdx.x & 31;
    int node = blockIdx.x * (blockDim.x >> 5) + warp;
    if (node >= NN) return;

    int start = g_offsets[node] + g_blkpre[node >> 8];
    int deg   = g_counts[node];

    float4 a0 = make_float4(0.f, 0.f, 0.f, 0.f);
    float4 a1 = make_float4(0.f, 0.f, 0.f, 0.f);
    int i = 0;
    for (; i + 3 < deg; i += 4) {
        int e0 = g_edge_ids[start + i];
        int e1 = g_edge_ids[start + i + 1];
        int e2 = g_edge_ids[start + i + 2];
        int e3 = g_edge_ids[start + i + 3];
        float4 v0 = ldcs4(edge_attrs + (size_t)e0 * D + lane * 4);
        float4 v1 = ldcs4(edge_attrs + (size_t)e1 * D + lane * 4);
        float4 v2 = ldcs4(edge_attrs + (size_t)e2 * D + lane * 4);
        float4 v3 = ldcs4(edge_attrs + (size_t)e3 * D + lane * 4);
        a0.x += v0.x + v2.x; a0.y += v0.y + v2.y;
        a0.z += v0.z + v2.z; a0.w += v0.w + v2.w;
        a1.x += v1.x + v3.x; a1.y += v1.y + v3.y;
        a1.z += v1.z + v3.z; a1.w += v1.w + v3.w;
    }
    for (; i < deg; i++) {
        int e0 = g_edge_ids[start + i];
        float4 v0 = ldcs4(edge_attrs + (size_t)e0 * D + lane * 4);
        a0.x += v0.x; a0.y += v0.y; a0.z += v0.z; a0.w += v0.w;
    }
    float inv = (deg > 0) ? (1.0f / (float)deg) : 0.0f;
    float4 r;
    r.x = (a0.x + a1.x) * inv;
    r.y = (a0.y + a1.y) * inv;
    r.z = (a0.z + a1.z) * inv;
    r.w = (a0.w + a1.w) * inv;
    *((float4*)(g_agg + (size_t)node * D) + lane) = r;
}

// ---------------- fused 2-layer MLP: A via smem, B direct from global -------
// smem: A stages 2x16KB @0, A2 frags 64KB @32KB -> 96KB total, 2 CTAs/SM
#define SM_SA(s) ((s) * 16384)
#define SM_A2 32768
#define MLP_SMEM 98304

__device__ __forceinline__ void mma_block_g(const char* sm, uint32_t abase,
                                            const uint4* __restrict__ wbase,
                                            int KT, int kt, int ktN,
                                            int wm, int wn, int lane,
                                            float Dm[2][8][4]) {
    uint4 ah[2], al[2];
#pragma unroll
    for (int mt = 0; mt < 2; mt++) {
        const uint4* p = (const uint4*)(sm + abase +
            (uint32_t)((((wm * 2 + mt) * KT + kt) * 32 + lane) * 32));
        ah[mt] = p[0];
        al[mt] = p[1];
    }
#pragma unroll
    for (int nt = 0; nt < 8; nt++) {
        uint4 b = __ldg(&wbase[(((wn * 8 + nt) * ktN) + kt) * 32 + lane]);
#pragma unroll
        for (int mt = 0; mt < 2; mt++) {
            mma_bf16(Dm[mt][nt], ah[mt].x, ah[mt].y, ah[mt].z, ah[mt].w, b.x, b.y);
            mma_bf16(Dm[mt][nt], ah[mt].x, ah[mt].y, ah[mt].z, ah[mt].w, b.z, b.w);
            mma_bf16(Dm[mt][nt], al[mt].x, al[mt].y, al[mt].z, al[mt].w, b.x, b.y);
        }
    }
}

__global__ void __launch_bounds__(256, 2)
k_mlp(const float* __restrict__ agg, const float* __restrict__ node,
      const float* __restrict__ c0, const float* __restrict__ b2,
      float* __restrict__ out) {
    extern __shared__ char sm[];
    int tid = threadIdx.x, lane = tid & 31, wid = tid >> 5;
    int wm = wid >> 1, wn = wid & 1;
    int m0 = blockIdx.x * 128;

    int srow = tid >> 1;
    int skt  = tid & 1;
    int smt  = srow >> 4;
    int slan = (srow & 7) * 4;
    int srh  = (srow >> 3) & 1;
    int gm   = m0 + srow;
    bool mok = (gm < NN);

    float D1[2][8][4];
#pragma unroll
    for (int a = 0; a < 2; a++)
#pragma unroll
        for (int b = 0; b < 8; b++)
#pragma unroll
            for (int q = 0; q < 4; q++) D1[a][b][q] = 0.f;

    float4 va[4];
    {
        int kc = skt * 16;
#pragma unroll
        for (int q = 0; q < 4; q++)
            va[q] = mok ? *(const float4*)(agg + (size_t)gm * D + kc + q * 4)
                        : make_float4(0.f, 0.f, 0.f, 0.f);
    }

    for (int s = 0; s < 8; s++) {
        int buf = s & 1;
        {
            float xs[16];
#pragma unroll
            for (int q = 0; q < 4; q++) {
                xs[q * 4 + 0] = va[q].x; xs[q * 4 + 1] = va[q].y;
                xs[q * 4 + 2] = va[q].z; xs[q * 4 + 3] = va[q].w;
            }
            uint32_t abase = SM_SA(buf) + (uint32_t)(((smt * 2 + skt) * 32) * 32);
#pragma unroll
            for (int p = 0; p < 8; p++) {
                uint32_t hi, lo;
                split_pair(xs[2 * p], xs[2 * p + 1], hi, lo);
                int c = p & 3, j = p >> 2;
                uint32_t off = abase + (uint32_t)((slan + c) * 32 + (srh + 2 * j) * 4);
                *(uint32_t*)(sm + off)      = hi;
                *(uint32_t*)(sm + off + 16) = lo;
            }
        }
        __syncthreads();
        if (s < 7) {
            const float* src = (s + 1 < 4) ? agg : node;
            int kc = ((s + 1) & 3) * 32 + skt * 16;
#pragma unroll
            for (int q = 0; q < 4; q++)
                va[q] = mok ? *(const float4*)(src + (size_t)gm * D + kc + q * 4)
                            : make_float4(0.f, 0.f, 0.f, 0.f);
        }
        const uint4* wb = g_W1f + s * 1024;
        mma_block_g(sm, SM_SA(buf), wb, 2, 0, 2, wm, wn, lane, D1);
        mma_block_g(sm, SM_SA(buf), wb, 2, 1, 2, wm, wn, lane, D1);
    }

    // epilogue-1: h = relu(D1 + c0) -> frag-major A2 (bf16 hi/lo)
    {
        int c = lane & 3;
#pragma unroll
        for (int mt = 0; mt < 2; mt++) {
#pragma unroll
            for (int nt = 0; nt < 8; nt++) {
                int col = wn * 64 + nt * 8 + 2 * c;
                float2 cv = *(const float2*)(c0 + col);
                float h0 = fmaxf(D1[mt][nt][0] + cv.x, 0.f);
                float h1 = fmaxf(D1[mt][nt][1] + cv.y, 0.f);
                float h2 = fmaxf(D1[mt][nt][2] + cv.x, 0.f);
                float h3 = fmaxf(D1[mt][nt][3] + cv.y, 0.f);
                uint32_t hi0, lo0, hi1, lo1;
                split_pair(h0, h1, hi0, lo0);
                split_pair(h2, h3, hi1, lo1);
                int mtile2 = wm * 2 + mt;
                int ktile2 = wn * 4 + (nt >> 1);
                int j2 = nt & 1;
                uint32_t base = SM_A2 +
                    (uint32_t)(((mtile2 * 8 + ktile2) * 32 + lane) * 32);
                *(uint32_t*)(sm + base + (0 + 2 * j2) * 4)      = hi0;
                *(uint32_t*)(sm + base + (0 + 2 * j2) * 4 + 16) = lo0;
                *(uint32_t*)(sm + base + (1 + 2 * j2) * 4)      = hi1;
                *(uint32_t*)(sm + base + (1 + 2 * j2) * 4 + 16) = lo1;
            }
        }
    }
    __syncthreads();

    float D2[2][8][4];
#pragma unroll
    for (int a = 0; a < 2; a++)
#pragma unroll
        for (int b = 0; b < 8; b++)
#pragma unroll
            for (int q = 0; q < 4; q++) D2[a][b][q] = 0.f;
#pragma unroll
    for (int kt = 0; kt < 8; kt++)
        mma_block_g(sm, SM_A2, g_W2f, 8, kt, 8, wm, wn, lane, D2);

    {
        int c = lane & 3, g = lane >> 2;
#pragma unroll
        for (int mt = 0; mt < 2; mt++) {
            int mrow = m0 + wm * 32 + mt * 16 + g;
#pragma unroll
            for (int nt = 0; nt < 8; nt++) {
                int col = wn * 64 + nt * 8 + 2 * c;
                float2 bv = *(const float2*)(b2 + col);
                if (mrow < NN) {
                    float2 o0 = make_float2(D2[mt][nt][0] + bv.x,
                                            D2[mt][nt][1] + bv.y);
                    *(float2*)(out + (size_t)mrow * D + col) = o0;
                }
                if (mrow + 8 < NN) {
                    float2 o1 = make_float2(D2[mt][nt][2] + bv.x,
                                            D2[mt][nt][3] + bv.y);
                    *(float2*)(out + (size_t)(mrow + 8) * D + col) = o1;
                }
            }
        }
    }

    // tail: re-zero counts for the next graph replay (counts are dead here;
    // first call relies on static zero-init). 391 blocks x 256 threads > NN.
    int gt = blockIdx.x * 256 + tid;
    if (gt < NN) g_counts[gt] = 0;
}

// ---------------- launch -----------------------------------------------------
extern "C" void kernel_launch(void* const* d_in, const int* in_sizes, int n_in,
                              void* d_out, int out_size) {
    const float* edge_attrs = (const float*)d_in[0];
    const float* node_attrs = (const float*)d_in[1];
    const float* gattr      = (const float*)d_in[2];
    const float* W1         = (const float*)d_in[3];
    const float* b1         = (const float*)d_in[4];
    const float* W2         = (const float*)d_in[5];
    const float* b2         = (const float*)d_in[6];
    const int*   edge_dst   = (const int*)d_in[7];
    float*       out        = (float*)d_out;

    float* agg_p; cudaGetSymbolAddress((void**)&agg_p, g_agg);
    float* c0_p;  cudaGetSymbolAddress((void**)&c0_p,  g_c0);

    static cudaStream_t s_side = nullptr;
    static cudaEvent_t  ev_prep = nullptr, ev_fork = nullptr;
    if (!s_side) {   // first call is the (non-captured) correctness run
        cudaStreamCreateWithFlags(&s_side, cudaStreamNonBlocking);
        cudaEventCreateWithFlags(&ev_prep, cudaEventDisableTiming);
        cudaEventCreateWithFlags(&ev_fork, cudaEventDisableTiming);
        cudaFuncSetAttribute(k_mlp, cudaFuncAttributeMaxDynamicSharedMemorySize,
                             MLP_SMEM);
    }

    // fork point: weight prep overlaps the CSR chain on a side stream
    cudaEventRecord(ev_fork, 0);
    cudaStreamWaitEvent(s_side, ev_fork, 0);
    k_prep<<<49, 256, 0, s_side>>>(gattr, W1, b1, W2);
    cudaEventRecord(ev_prep, s_side);

    k_count_pos<<<(NE + 255) / 256, 256>>>(edge_dst);
    k_scan1<<<NBLK, 256>>>();
    k_scan2<<<1, 256>>>();
    k_scatter<<<(NE + 255) / 256, 256>>>(edge_dst);
    k_aggregate<<<(NN + 7) / 8, 256>>>(edge_attrs);

    cudaStreamWaitEvent(0, ev_prep, 0);
    int mb = (NN + 127) / 128;
    k_mlp<<<mb, 256, MLP_SMEM>>>(agg_p, node_attrs, c0_p, b2, out);
}